// round 2
// baseline (speedup 1.0000x reference)
#include <cuda_runtime.h>
#include <cstdint>

// Problem constants (from reference): N=50000, E=640000, D=H=128, OUT=32
#define MAXN 50000
#define MAXE 640000

// Scratch (device globals — no allocation allowed)
__device__ float g_W3[128 * 512];     // [Wp | Wp@WmA | Wp@WmB | Wp@WuA]
__device__ float g_b3[512];           // [bp | bp@WmA | bp@WmB+bm | bp@WuA]
__device__ float g_Y[MAXN * 512];     // per node: h0 | a | b | c
__device__ float g_upd[MAXN * 128];   // pooled @ WuB + bu
__device__ float g_pool[MAXN * 128];  // segment sums
__device__ float g_cnt[MAXN];         // segment counts
__device__ float g_gsum[128];         // graph-level sum of normalized hn

// ---------------------------------------------------------------------------
// Zero the accumulators (graph replays re-run this every launch)
// ---------------------------------------------------------------------------
__global__ void k_zero(int n) {
    int i = blockIdx.x * blockDim.x + threadIdx.x;
    int np = n * 128;
    int total = np + n + 128;
    if (i >= total) return;
    if (i < np)            g_pool[i] = 0.f;
    else if (i < np + n)   g_cnt[i - np] = 0.f;
    else                   g_gsum[i - np - n] = 0.f;
}

// ---------------------------------------------------------------------------
// Build combined weights/biases: W3 = [Wp | Wp@WmA | Wp@WmB | Wp@WuA]
// ---------------------------------------------------------------------------
__global__ void k_prep(const float* __restrict__ Wp, const float* __restrict__ bp,
                       const float* __restrict__ Wm, const float* __restrict__ bm,
                       const float* __restrict__ Wu) {
    int idx = blockIdx.x * blockDim.x + threadIdx.x;
    if (idx < 128 * 512) {
        int i = idx >> 9;        // row in [0,128)
        int j = idx & 511;       // col in [0,512)
        int blk = j >> 7, jj = j & 127;
        float v;
        if (blk == 0) {
            v = Wp[i * 128 + jj];
        } else {
            const float* M = (blk == 1) ? Wm : (blk == 2 ? Wm + 16384 : Wu);
            float s = 0.f;
            for (int k = 0; k < 128; k++) s += Wp[i * 128 + k] * M[k * 128 + jj];
            v = s;
        }
        g_W3[idx] = v;
    }
    if (idx < 512) {
        int blk = idx >> 7, jj = idx & 127;
        float v;
        if (blk == 0) {
            v = bp[jj];
        } else {
            const float* M = (blk == 1) ? Wm : (blk == 2 ? Wm + 16384 : Wu);
            float s = (blk == 2) ? bm[jj] : 0.f;
            for (int k = 0; k < 128; k++) s += bp[k] * M[k * 128 + jj];
            v = s;
        }
        g_b3[idx] = v;
    }
}

// ---------------------------------------------------------------------------
// Tiled fp32 GEMM: 64x64 tile, K=128 (two 64-K stages), 256 threads, 4x4/thread
// mode 0: g_Y[n,512] = x[n,128] @ g_W3[128,512] + g_b3
// mode 1: g_upd[n,128] = (g_pool/max(cnt,1))[n,128] @ Wext[128,128] + biasExt
// ---------------------------------------------------------------------------
__global__ void __launch_bounds__(256) k_gemm(const float* __restrict__ Xext,
                                              const float* __restrict__ Wext,
                                              const float* __restrict__ biasExt,
                                              int n, int mode) {
    __shared__ __align__(16) float As[64][65];
    __shared__ __align__(16) float Bs[64][68];

    const float* X    = mode ? g_pool : Xext;
    const float* W    = mode ? Wext   : g_W3;
    const float* bias = mode ? biasExt : g_b3;
    float* Yout       = mode ? g_upd  : g_Y;
    const int p4      = mode ? 32 : 128;   // both W row pitch and out row pitch, in float4

    int tid = threadIdx.x;
    int tx = tid & 15, ty = tid >> 4;
    int rowBase = blockIdx.y * 64;
    int cb4 = blockIdx.x * 16;             // column base / 4

    float acc[4][4] = {};

    for (int kt = 0; kt < 2; kt++) {
        // Load A tile: 64 rows x 64 k (row-major in smem, coalesced global loads)
        #pragma unroll
        for (int it = 0; it < 4; it++) {
            int i = tid + it * 256;
            int m = i >> 4, k4 = i & 15;
            int row = rowBase + m;
            float4 v = make_float4(0.f, 0.f, 0.f, 0.f);
            if (row < n) {
                v = ((const float4*)X)[row * 32 + kt * 16 + k4];
                if (mode) {
                    float rc = 1.0f / fmaxf(g_cnt[row], 1.0f);
                    v.x *= rc; v.y *= rc; v.z *= rc; v.w *= rc;
                }
            }
            As[m][k4 * 4 + 0] = v.x; As[m][k4 * 4 + 1] = v.y;
            As[m][k4 * 4 + 2] = v.z; As[m][k4 * 4 + 3] = v.w;
        }
        // Load B tile: 64 k x 64 cols
        #pragma unroll
        for (int it = 0; it < 4; it++) {
            int i = tid + it * 256;
            int kk = i >> 4, n4 = i & 15;
            float4 w = ((const float4*)W)[(kt * 64 + kk) * p4 + cb4 + n4];
            Bs[kk][n4 * 4 + 0] = w.x; Bs[kk][n4 * 4 + 1] = w.y;
            Bs[kk][n4 * 4 + 2] = w.z; Bs[kk][n4 * 4 + 3] = w.w;
        }
        __syncthreads();

        #pragma unroll
        for (int k = 0; k < 64; k++) {
            float4 b = *reinterpret_cast<const float4*>(&Bs[k][tx * 4]);
            float a0 = As[ty * 4 + 0][k];
            float a1 = As[ty * 4 + 1][k];
            float a2 = As[ty * 4 + 2][k];
            float a3 = As[ty * 4 + 3][k];
            acc[0][0] += a0 * b.x; acc[0][1] += a0 * b.y; acc[0][2] += a0 * b.z; acc[0][3] += a0 * b.w;
            acc[1][0] += a1 * b.x; acc[1][1] += a1 * b.y; acc[1][2] += a1 * b.z; acc[1][3] += a1 * b.w;
            acc[2][0] += a2 * b.x; acc[2][1] += a2 * b.y; acc[2][2] += a2 * b.z; acc[2][3] += a2 * b.w;
            acc[3][0] += a3 * b.x; acc[3][1] += a3 * b.y; acc[3][2] += a3 * b.z; acc[3][3] += a3 * b.w;
        }
        __syncthreads();
    }

    float4 bv = ((const float4*)bias)[cb4 + tx];
    #pragma unroll
    for (int q = 0; q < 4; q++) {
        int row = rowBase + ty * 4 + q;
        if (row < n) {
            float4 o;
            o.x = acc[q][0] + bv.x; o.y = acc[q][1] + bv.y;
            o.z = acc[q][2] + bv.z; o.w = acc[q][3] + bv.w;
            ((float4*)Yout)[row * p4 + cb4 + tx] = o;
        }
    }
}

// ---------------------------------------------------------------------------
// Edge kernel: one warp per edge. msg = relu(a[src]+b[dst]); red.v4 into pool.
// a/b rows live in g_Y (L2-resident, ~77MB working set).
// ---------------------------------------------------------------------------
__global__ void __launch_bounds__(256) k_edge(const int* __restrict__ src,
                                              const int* __restrict__ dst, int e) {
    int wid = (blockIdx.x * blockDim.x + threadIdx.x) >> 5;
    if (wid >= e) return;
    int lane = threadIdx.x & 31;
    int s = __ldg(src + wid);
    int d = __ldg(dst + wid);

    const float4* Y4 = (const float4*)g_Y;
    float4 va = __ldg(Y4 + (size_t)s * 128 + 32 + lane);   // a block: cols 128..255
    float4 vb = __ldg(Y4 + (size_t)d * 128 + 64 + lane);   // b block: cols 256..383
    float4 m;
    m.x = fmaxf(va.x + vb.x, 0.f);
    m.y = fmaxf(va.y + vb.y, 0.f);
    m.z = fmaxf(va.z + vb.z, 0.f);
    m.w = fmaxf(va.w + vb.w, 0.f);

    float* p = g_pool + (size_t)d * 128 + lane * 4;
    asm volatile("red.global.add.v4.f32 [%0], {%1,%2,%3,%4};"
                 :: "l"(p), "f"(m.x), "f"(m.y), "f"(m.z), "f"(m.w) : "memory");
    if (lane == 0) atomicAdd(g_cnt + d, 1.0f);
}

// ---------------------------------------------------------------------------
// Fused relu + LayerNorm + graph mean-pool partial sums. Warp per row.
// hn = relu(h0 + c + upd); LN over 128 features; accumulate into g_gsum.
// ---------------------------------------------------------------------------
__global__ void __launch_bounds__(256) k_ln(const float* __restrict__ gamma,
                                            const float* __restrict__ beta, int n) {
    __shared__ float sacc[8][128];
    int lane = threadIdx.x & 31;
    int w = threadIdx.x >> 5;
    int gw = blockIdx.x * 8 + w;
    int nw = gridDim.x * 8;

    float4 ga = ((const float4*)gamma)[lane];
    float4 be = ((const float4*)beta)[lane];
    float ax = 0.f, ay = 0.f, az = 0.f, aw = 0.f;

    for (int row = gw; row < n; row += nw) {
        const float4* yr = ((const float4*)g_Y) + (size_t)row * 128;
        float4 h0 = __ldg(yr + lane);        // h0 block: cols 0..127
        float4 cv = __ldg(yr + 96 + lane);   // c  block: cols 384..511
        float4 up = __ldg(((const float4*)g_upd) + (size_t)row * 32 + lane);
        float vx = fmaxf(h0.x + cv.x + up.x, 0.f);
        float vy = fmaxf(h0.y + cv.y + up.y, 0.f);
        float vz = fmaxf(h0.z + cv.z + up.z, 0.f);
        float vw = fmaxf(h0.w + cv.w + up.w, 0.f);

        float s1 = vx + vy + vz + vw;
        float s2 = vx * vx + vy * vy + vz * vz + vw * vw;
        #pragma unroll
        for (int o = 16; o > 0; o >>= 1) {
            s1 += __shfl_xor_sync(0xFFFFFFFFu, s1, o);
            s2 += __shfl_xor_sync(0xFFFFFFFFu, s2, o);
        }
        float mu  = s1 * (1.f / 128.f);
        float var = s2 * (1.f / 128.f) - mu * mu;
        float is  = rsqrtf(var + 1e-6f);
        ax += (vx - mu) * is * ga.x + be.x;
        ay += (vy - mu) * is * ga.y + be.y;
        az += (vz - mu) * is * ga.z + be.z;
        aw += (vw - mu) * is * ga.w + be.w;
    }

    sacc[w][lane * 4 + 0] = ax;
    sacc[w][lane * 4 + 1] = ay;
    sacc[w][lane * 4 + 2] = az;
    sacc[w][lane * 4 + 3] = aw;
    __syncthreads();
    int t = threadIdx.x;
    if (t < 128) {
        float s = 0.f;
        #pragma unroll
        for (int ww = 0; ww < 8; ww++) s += sacc[ww][t];
        atomicAdd(&g_gsum[t], s);
    }
}

// ---------------------------------------------------------------------------
// Final: out[1,32] = (gsum/n) @ Wd + bd
// ---------------------------------------------------------------------------
__global__ void k_final(const float* __restrict__ Wd, const float* __restrict__ bd,
                        float* __restrict__ out, int n) {
    int o = threadIdx.x;
    if (o >= 32) return;
    float s = 0.f;
    #pragma unroll
    for (int c = 0; c < 128; c++) s += g_gsum[c] * Wd[c * 32 + o];
    out[o] = s / (float)n + bd[o];
}

// ---------------------------------------------------------------------------
extern "C" void kernel_launch(void* const* d_in, const int* in_sizes, int n_in,
                              void* d_out, int out_size) {
    const float* x     = (const float*)d_in[0];
    const int*   esrc  = (const int*)d_in[1];
    const int*   edst  = (const int*)d_in[2];
    const float* Wp    = (const float*)d_in[3];
    const float* bp    = (const float*)d_in[4];
    const float* Wm    = (const float*)d_in[5];
    const float* bm    = (const float*)d_in[6];
    const float* Wu    = (const float*)d_in[7];
    const float* bu    = (const float*)d_in[8];
    const float* gamma = (const float*)d_in[9];
    const float* beta  = (const float*)d_in[10];
    const float* Wd    = (const float*)d_in[11];
    const float* bd    = (const float*)d_in[12];
    float* out = (float*)d_out;

    int n = in_sizes[0] / 128;
    int e = in_sizes[1];
    int rb = (n + 63) / 64;

    k_zero<<<(n * 129 + 128 + 255) / 256, 256>>>(n);
    k_prep<<<256, 256>>>(Wp, bp, Wm, bm, Wu);
    // Y = x @ W3 + b3  -> h0 | a | b | c
    k_gemm<<<dim3(8, rb), 256>>>(x, nullptr, nullptr, n, 0);
    // scatter edge messages
    k_edge<<<(e + 7) / 8, 256>>>(esrc, edst, e);
    // upd = pooled @ WuB + bu
    k_gemm<<<dim3(2, rb), 256>>>(nullptr, Wu + 16384, bu, n, 1);
    // relu + LN + graph pool
    k_ln<<<1024, 256>>>(gamma, beta, n);
    k_final<<<1, 32>>>(Wd, bd, out, n);
}